// round 2
// baseline (speedup 1.0000x reference)
#include <cuda_runtime.h>

// ---------------------------------------------------------------------------
// TrackCrop: input [32, 512, 512, 3] f32.
// Per batch: count nonzeros + coordinate-weighted sums -> centroid -> clamped
// 256x256 crop origin -> gather crop.
//
// Two kernels, no zero pass: reduce uses a last-block-per-batch ticket; the
// finalizing block reads-and-resets the accumulators with atomicExch (leaving
// them 0 for the next graph replay) and publishes the crop origin in g_HW.
// ---------------------------------------------------------------------------

#define NBATCH 32
#define SY 512
#define SX 512
#define NC 3
#define ROW_FLOATS (SX * NC)        // 1536 floats per row
#define CROP 256
#define OUT_ROW_FLOATS (CROP * NC)  // 768

__device__ int  g_cnt[NBATCH];   // zero-init at load; returned to 0 every run
__device__ int  g_sx[NBATCH];
__device__ int  g_sy[NBATCH];
__device__ int  g_tick[NBATCH];
__device__ int2 g_HW[NBATCH];    // (H, W) crop origin per batch

// One block (128 threads) per image row.
__global__ __launch_bounds__(128) void reduce_kernel(const float* __restrict__ in) {
    const int y = blockIdx.x;   // 0..511
    const int b = blockIdx.y;   // 0..31
    const int t = threadIdx.x;  // 0..127

    const float4* __restrict__ row =
        (const float4*)(in + ((size_t)b * SY + y) * ROW_FLOATS);

    int cnt = 0;
    int sx  = 0;
    #pragma unroll
    for (int i = 0; i < 3; i++) {
        const int q = t + i * 128;      // float4 index within row, < 384
        const float4 v = row[q];
        const int j = 4 * q;            // float index within row
        if (v.x != 0.0f) { cnt++; sx += (j    ) / 3; }
        if (v.y != 0.0f) { cnt++; sx += (j + 1) / 3; }
        if (v.z != 0.0f) { cnt++; sx += (j + 2) / 3; }
        if (v.w != 0.0f) { cnt++; sx += (j + 3) / 3; }
    }

    // warp reduce
    #pragma unroll
    for (int o = 16; o > 0; o >>= 1) {
        cnt += __shfl_down_sync(0xFFFFFFFFu, cnt, o);
        sx  += __shfl_down_sync(0xFFFFFFFFu, sx,  o);
    }

    __shared__ int s_cnt, s_sx;
    if (t == 0) { s_cnt = 0; s_sx = 0; }
    __syncthreads();
    if ((t & 31) == 0) {
        atomicAdd(&s_cnt, cnt);
        atomicAdd(&s_sx,  sx);
    }
    __syncthreads();

    if (t == 0) {
        atomicAdd(&g_cnt[b], s_cnt);
        atomicAdd(&g_sx[b],  s_sx);
        atomicAdd(&g_sy[b],  y * s_cnt);
        __threadfence();
        if (atomicAdd(&g_tick[b], 1) == SY - 1) {
            // Last block for this batch: read+reset accumulators (leaves
            // scratch at 0 for the next graph replay), publish crop origin.
            const int c  = atomicExch(&g_cnt[b], 0);
            const int xs = atomicExch(&g_sx[b],  0);
            const int ys = atomicExch(&g_sy[b],  0);
            atomicExch(&g_tick[b], 0);
            // Match reference numerics exactly: int32 -> f32 (RN), IEEE f32
            // divide, truncating cast to int32.
            const float fc = __int2float_rn(c);
            const int xc = (int)__fdiv_rn(__int2float_rn(xs), fc);
            const int yc = (int)__fdiv_rn(__int2float_rn(ys), fc);
            int2 hw;
            hw.x = min(max(yc - CROP / 2, 0), SY - 1 - CROP);   // H in [0,255]
            hw.y = min(max(xc - CROP / 2, 0), SX - 1 - CROP);   // W in [0,255]
            g_HW[b] = hw;
        }
    }
}

// One block (192 threads) per output row; each thread copies 4 floats.
// Source is only 4B-aligned (W*3 arbitrary), dest is 16B-aligned.
__global__ __launch_bounds__(192) void crop_kernel(const float* __restrict__ in,
                                                   float* __restrict__ out) {
    const int r = blockIdx.x;   // output row 0..255
    const int b = blockIdx.y;   // batch
    const int t = threadIdx.x;  // 0..191

    const int2 hw = g_HW[b];    // (H, W)

    const float* __restrict__ src =
        in + (size_t)b * (SY * SX * NC)
           + ((size_t)(hw.x + r) * SX + hw.y) * NC
           + 4 * t;
    float4* __restrict__ dst =
        (float4*)(out + ((size_t)b * CROP + r) * OUT_ROW_FLOATS) + t;

    float4 v;
    v.x = src[0];
    v.y = src[1];
    v.z = src[2];
    v.w = src[3];
    *dst = v;
}

extern "C" void kernel_launch(void* const* d_in, const int* in_sizes, int n_in,
                              void* d_out, int out_size) {
    const float* in = (const float*)d_in[0];
    float* out = (float*)d_out;

    reduce_kernel<<<dim3(SY, NBATCH), 128>>>(in);
    crop_kernel<<<dim3(CROP, NBATCH), 192>>>(in, out);
}

// round 3
// speedup vs baseline: 1.2154x; 1.2154x over previous
#include <cuda_runtime.h>

// ---------------------------------------------------------------------------
// TrackCrop: input [32, 512, 512, 3] f32.
// reduce: nonzero count + x/y weighted sums per batch -> centroid -> crop
// origin (published in g_HW, scratch self-resetting for graph replay).
// crop: gather 256x256x3 window.
// ---------------------------------------------------------------------------

#define NBATCH 32
#define SY 512
#define SX 512
#define NC 3
#define ROW_FLOATS (SX * NC)        // 1536
#define ROW_F4 (ROW_FLOATS / 4)     // 384
#define CROP 256
#define OUT_ROW_FLOATS (CROP * NC)  // 768

#define RB 32                       // rows per reduce block
#define RBLOCKS_PER_BATCH (SY / RB) // 16

#define CR 8                        // rows per crop block
#define CBLOCKS_PER_BATCH (CROP / CR) // 32

__device__ int  g_cnt[NBATCH];   // zero at load; returned to 0 every run
__device__ int  g_sx[NBATCH];
__device__ int  g_sy[NBATCH];
__device__ int  g_tick[NBATCH];
__device__ int2 g_HW[NBATCH];    // (H, W) crop origin per batch

// 128 threads, 32 rows per block. Per-thread x-weights are hoisted out of
// the row loop (they depend only on threadIdx), so the inner loop is pure
// load + compare + predicated add.
__global__ __launch_bounds__(128) void reduce_kernel(const float* __restrict__ in) {
    const int t  = threadIdx.x;             // 0..127
    const int b  = blockIdx.y;              // 0..31
    const int y0 = blockIdx.x * RB;         // 0,32,...,480

    // Precompute x coordinate for each of this thread's 12 float lanes.
    int xc[12];
    #pragma unroll
    for (int i = 0; i < 3; i++) {
        const int j = 4 * (t + i * 128);    // float index within row
        #pragma unroll
        for (int k = 0; k < 4; k++)
            xc[i * 4 + k] = (j + k) / 3;    // magic-mul division, done once
    }

    const float4* __restrict__ base =
        (const float4*)(in + ((size_t)b * SY + y0) * ROW_FLOATS);

    int cnt = 0, sx = 0, sy = 0;
    #pragma unroll 4
    for (int r = 0; r < RB; r++) {
        const float4* __restrict__ row = base + (size_t)r * ROW_F4;
        int rc = 0;
        #pragma unroll
        for (int i = 0; i < 3; i++) {
            const float4 v = row[t + i * 128];
            if (v.x != 0.0f) { rc++; sx += xc[i * 4 + 0]; }
            if (v.y != 0.0f) { rc++; sx += xc[i * 4 + 1]; }
            if (v.z != 0.0f) { rc++; sx += xc[i * 4 + 2]; }
            if (v.w != 0.0f) { rc++; sx += xc[i * 4 + 3]; }
        }
        cnt += rc;
        sy  += (y0 + r) * rc;
    }

    // warp reduce
    #pragma unroll
    for (int o = 16; o > 0; o >>= 1) {
        cnt += __shfl_down_sync(0xFFFFFFFFu, cnt, o);
        sx  += __shfl_down_sync(0xFFFFFFFFu, sx,  o);
        sy  += __shfl_down_sync(0xFFFFFFFFu, sy,  o);
    }

    __shared__ int s_cnt, s_sx, s_sy;
    if (t == 0) { s_cnt = 0; s_sx = 0; s_sy = 0; }
    __syncthreads();
    if ((t & 31) == 0) {
        atomicAdd(&s_cnt, cnt);
        atomicAdd(&s_sx,  sx);
        atomicAdd(&s_sy,  sy);
    }
    __syncthreads();

    if (t == 0) {
        atomicAdd(&g_cnt[b], s_cnt);
        atomicAdd(&g_sx[b],  s_sx);
        atomicAdd(&g_sy[b],  s_sy);
        __threadfence();
        if (atomicAdd(&g_tick[b], 1) == RBLOCKS_PER_BATCH - 1) {
            // Last block for this batch: read+reset (scratch back to 0 for
            // the next graph replay), publish crop origin.
            const int c  = atomicExch(&g_cnt[b], 0);
            const int xs = atomicExch(&g_sx[b],  0);
            const int ys = atomicExch(&g_sy[b],  0);
            atomicExch(&g_tick[b], 0);
            // Reference numerics: int32->f32 RN, IEEE f32 divide, trunc cast.
            const float fc = __int2float_rn(c);
            const int xcm = (int)__fdiv_rn(__int2float_rn(xs), fc);
            const int ycm = (int)__fdiv_rn(__int2float_rn(ys), fc);
            int2 hw;
            hw.x = min(max(ycm - CROP / 2, 0), SY - 1 - CROP);  // H
            hw.y = min(max(xcm - CROP / 2, 0), SX - 1 - CROP);  // W
            g_HW[b] = hw;
        }
    }
}

// 192 threads, 8 output rows per block. Source is only 4B-aligned
// (W*3 arbitrary) -> scalar loads; dest row is 16B-aligned -> float4 store.
__global__ __launch_bounds__(192) void crop_kernel(const float* __restrict__ in,
                                                   float* __restrict__ out) {
    const int t  = threadIdx.x;          // 0..191
    const int b  = blockIdx.y;           // batch
    const int r0 = blockIdx.x * CR;      // first output row of this block

    const int2 hw = g_HW[b];             // (H, W)

    const float* __restrict__ srcb =
        in + (size_t)b * (SY * SX * NC)
           + ((size_t)(hw.x + r0) * SX + hw.y) * NC
           + 4 * t;
    float4* __restrict__ dstb =
        (float4*)(out + ((size_t)b * CROP + r0) * OUT_ROW_FLOATS) + t;

    #pragma unroll
    for (int r = 0; r < CR; r++) {
        const float* __restrict__ src = srcb + (size_t)r * ROW_FLOATS;
        float4 v;
        v.x = src[0];
        v.y = src[1];
        v.z = src[2];
        v.w = src[3];
        dstb[(size_t)r * (OUT_ROW_FLOATS / 4)] = v;
    }
}

extern "C" void kernel_launch(void* const* d_in, const int* in_sizes, int n_in,
                              void* d_out, int out_size) {
    const float* in = (const float*)d_in[0];
    float* out = (float*)d_out;

    reduce_kernel<<<dim3(RBLOCKS_PER_BATCH, NBATCH), 128>>>(in);
    crop_kernel<<<dim3(CBLOCKS_PER_BATCH, NBATCH), 192>>>(in, out);
}